// round 3
// baseline (speedup 1.0000x reference)
#include <cuda_runtime.h>

// ---------------------------------------------------------------------------
// Attention: O = softmax((X Wq)(X Wk)^T / sqrt(Dqkv)) (X Wv)
// B=4, S=2048, D=1024, DQKV=1024, fp32.
//
// Plan (5 graph-capturable launches, no allocations):
//   1-3. Q/K/V = X @ W{q,k,v}           (NN sgemm, M=8192 N=1024 K=1024)
//   4.   S = (Q K^T) * (1/32)           (NT batched sgemm, M=N=2048 K=1024, z=4)
//   5.   rowwise softmax on S in place
//   6.   O = S @ V                      (NN batched sgemm, M=2048 N=1024 K=2048, z=4)
// ---------------------------------------------------------------------------

#define BM 128
#define BN 128
#define BK 8
#define TM 8
#define TN 8
#define NTHREADS 256

static const int Bv   = 4;
static const int Sv   = 2048;
static const int Dv   = 1024;
static const int DQKV = 1024;

// Scratch (allocation-free per harness rules): 3x32MB + 64MB
__device__ __align__(16) float g_Q[(size_t)Bv * Sv * DQKV];
__device__ __align__(16) float g_K[(size_t)Bv * Sv * DQKV];
__device__ __align__(16) float g_V[(size_t)Bv * Sv * DQKV];
__device__ __align__(16) float g_S[(size_t)Bv * Sv * Sv];

// Classic register-blocked SGEMM. C[M,N] = alpha * A[M,K] @ op(B).
// TRANS_B=false: B is [K,N] row-major. TRANS_B=true: B is [N,K] row-major (B^T used).
// All of M,N divisible by 128, K divisible by 8 for this problem — no bounds checks.
template <bool TRANS_B>
__global__ __launch_bounds__(NTHREADS)
void sgemm_kernel(const float* __restrict__ A, const float* __restrict__ B,
                  float* __restrict__ C, int M, int N, int K, float alpha,
                  size_t strideA, size_t strideB, size_t strideC)
{
    A += (size_t)blockIdx.z * strideA;
    B += (size_t)blockIdx.z * strideB;
    C += (size_t)blockIdx.z * strideC;

    __shared__ float As[BK][BM];
    __shared__ float Bs[BK][BN];

    const int tid = threadIdx.x;
    const int cRow0 = blockIdx.y * BM;
    const int cCol0 = blockIdx.x * BN;

    // A tile load map: 256 threads x float4 covers 128x8.
    const int aRow = tid >> 1;             // 0..127
    const int aCol = (tid & 1) * 4;        // 0 or 4
    // B tile load map (NN): 8x128, float4 along N.
    const int bRow = tid >> 5;             // 0..7
    const int bCol = (tid & 31) * 4;       // 0..124

    // Per-thread output tile coords.
    const int trow = (tid / (BN / TN)) * TM;   // 0..120 step 8
    const int tcol = (tid % (BN / TN)) * TN;   // 0..120 step 8

    float acc[TM][TN];
    #pragma unroll
    for (int i = 0; i < TM; i++)
        #pragma unroll
        for (int j = 0; j < TN; j++) acc[i][j] = 0.0f;

    for (int kt = 0; kt < K; kt += BK) {
        // Load A tile (transpose into As[k][m])
        float4 a4 = *reinterpret_cast<const float4*>(
            &A[(size_t)(cRow0 + aRow) * K + kt + aCol]);
        As[aCol + 0][aRow] = a4.x;
        As[aCol + 1][aRow] = a4.y;
        As[aCol + 2][aRow] = a4.z;
        As[aCol + 3][aRow] = a4.w;

        if (TRANS_B) {
            // B is [N,K] row-major; need Bs[k][n] = B[n, kt+k]
            float4 b4 = *reinterpret_cast<const float4*>(
                &B[(size_t)(cCol0 + aRow) * K + kt + aCol]);
            Bs[aCol + 0][aRow] = b4.x;
            Bs[aCol + 1][aRow] = b4.y;
            Bs[aCol + 2][aRow] = b4.z;
            Bs[aCol + 3][aRow] = b4.w;
        } else {
            float4 b4 = *reinterpret_cast<const float4*>(
                &B[(size_t)(kt + bRow) * N + cCol0 + bCol]);
            *reinterpret_cast<float4*>(&Bs[bRow][bCol]) = b4;
        }
        __syncthreads();

        #pragma unroll
        for (int k = 0; k < BK; ++k) {
            float regM[TM], regN[TN];
            *reinterpret_cast<float4*>(&regM[0]) =
                *reinterpret_cast<const float4*>(&As[k][trow]);
            *reinterpret_cast<float4*>(&regM[4]) =
                *reinterpret_cast<const float4*>(&As[k][trow + 4]);
            *reinterpret_cast<float4*>(&regN[0]) =
                *reinterpret_cast<const float4*>(&Bs[k][tcol]);
            *reinterpret_cast<float4*>(&regN[4]) =
                *reinterpret_cast<const float4*>(&Bs[k][tcol + 4]);
            #pragma unroll
            for (int i = 0; i < TM; i++)
                #pragma unroll
                for (int j = 0; j < TN; j++)
                    acc[i][j] = fmaf(regM[i], regN[j], acc[i][j]);
        }
        __syncthreads();
    }

    #pragma unroll
    for (int i = 0; i < TM; i++) {
        const size_t row = (size_t)(cRow0 + trow + i);
        #pragma unroll
        for (int j = 0; j < TN; j += 4) {
            float4 v;
            v.x = acc[i][j + 0] * alpha;
            v.y = acc[i][j + 1] * alpha;
            v.z = acc[i][j + 2] * alpha;
            v.w = acc[i][j + 3] * alpha;
            *reinterpret_cast<float4*>(&C[row * N + cCol0 + tcol + j]) = v;
        }
    }
}

// In-place row softmax. One block per row of length n (n % (256*4) == 0 here).
__global__ __launch_bounds__(256)
void softmax_kernel(float* __restrict__ S, int n)
{
    float* row = S + (size_t)blockIdx.x * n;
    const int tid = threadIdx.x;
    __shared__ float red[256];

    // Pass 1: max
    float lmax = -1e30f;
    for (int i = tid * 4; i < n; i += 256 * 4) {
        float4 v = *reinterpret_cast<const float4*>(&row[i]);
        lmax = fmaxf(lmax, fmaxf(fmaxf(v.x, v.y), fmaxf(v.z, v.w)));
    }
    red[tid] = lmax;
    __syncthreads();
    for (int s = 128; s > 0; s >>= 1) {
        if (tid < s) red[tid] = fmaxf(red[tid], red[tid + s]);
        __syncthreads();
    }
    const float m = red[0];
    __syncthreads();

    // Pass 2: exp + sum
    float lsum = 0.0f;
    for (int i = tid * 4; i < n; i += 256 * 4) {
        float4 v = *reinterpret_cast<float4*>(&row[i]);
        v.x = __expf(v.x - m);
        v.y = __expf(v.y - m);
        v.z = __expf(v.z - m);
        v.w = __expf(v.w - m);
        lsum += (v.x + v.y) + (v.z + v.w);
        *reinterpret_cast<float4*>(&row[i]) = v;
    }
    red[tid] = lsum;
    __syncthreads();
    for (int s = 128; s > 0; s >>= 1) {
        if (tid < s) red[tid] += red[tid + s];
        __syncthreads();
    }
    const float inv = 1.0f / red[0];

    // Pass 3: normalize
    for (int i = tid * 4; i < n; i += 256 * 4) {
        float4 v = *reinterpret_cast<float4*>(&row[i]);
        v.x *= inv; v.y *= inv; v.z *= inv; v.w *= inv;
        *reinterpret_cast<float4*>(&row[i]) = v;
    }
}

extern "C" void kernel_launch(void* const* d_in, const int* in_sizes, int n_in,
                              void* d_out, int out_size)
{
    const float* x  = (const float*)d_in[0];
    const float* wq = (const float*)d_in[1];
    const float* wk = (const float*)d_in[2];
    const float* wv = (const float*)d_in[3];
    float* out = (float*)d_out;

    float *Q, *K, *V, *S;
    cudaGetSymbolAddress((void**)&Q, g_Q);
    cudaGetSymbolAddress((void**)&K, g_K);
    cudaGetSymbolAddress((void**)&V, g_V);
    cudaGetSymbolAddress((void**)&S, g_S);

    const int MS = Bv * Sv;              // 8192 flattened rows
    const float inv_sqrt_d = 0.03125f;   // 1/sqrt(1024)

    // 1-3) QKV projections: [8192,1024] @ [1024,1024]
    {
        dim3 grid(DQKV / BN, MS / BM, 1);
        sgemm_kernel<false><<<grid, NTHREADS>>>(x, wq, Q, MS, DQKV, Dv, 1.0f, 0, 0, 0);
        sgemm_kernel<false><<<grid, NTHREADS>>>(x, wk, K, MS, DQKV, Dv, 1.0f, 0, 0, 0);
        sgemm_kernel<false><<<grid, NTHREADS>>>(x, wv, V, MS, DQKV, Dv, 1.0f, 0, 0, 0);
    }

    // 4) scores: per-batch Q_b @ K_b^T * (1/32)
    {
        dim3 grid(Sv / BN, Sv / BM, Bv);
        sgemm_kernel<true><<<grid, NTHREADS>>>(
            Q, K, S, Sv, Sv, DQKV, inv_sqrt_d,
            (size_t)Sv * DQKV, (size_t)Sv * DQKV, (size_t)Sv * Sv);
    }

    // 5) softmax over last dim, in place
    softmax_kernel<<<Bv * Sv, 256>>>(S, Sv);

    // 6) output: per-batch P_b @ V_b -> d_out
    {
        dim3 grid(DQKV / BN, Sv / BM, Bv);
        sgemm_kernel<false><<<grid, NTHREADS>>>(
            S, V, out, Sv, DQKV, Sv, 1.0f,
            (size_t)Sv * Sv, (size_t)Sv * DQKV, (size_t)Sv * DQKV);
    }
}

// round 8
// speedup vs baseline: 2.2299x; 2.2299x over previous
#include <cuda_runtime.h>
#include <cuda_bf16.h>
#include <cstdint>

// ---------------------------------------------------------------------------
// Attention via legacy warp-MMA (mma.sync bf16, sm_80-level PTX — compiles at
// compute_103 where tcgen05 does not).
//   O = softmax((X Wq)(X Wk)^T / 32) (X Wv),  B=4 S=2048 D=DQKV=1024, fp32 I/O.
//
// Every GEMM is D[m,n] = sum_k A[m,k]*B[n,k]  (A:[M,K], B:[N,K], both K-major).
// fp32 operands split x = hi + lo (bf16); GEMM = Ah*Bh + Ah*Bl + Al*Bh with
// fp32 accumulators -> ~1e-5 relative error.
// ---------------------------------------------------------------------------

static const int Bv = 4, Sv = 2048, Dv = 1024, DQ = 1024;
static const int MS = Bv * Sv; // 8192

#define TILE 128
#define KCH 32                    // K elements per mainloop chunk
#define KPAD 40                   // padded smem K-stride (80B) -> ldmatrix conflict-free
#define GEMM_THREADS 256
#define BUFB (128 * KPAD * 2)     // 10240 B per operand buffer
#define STAGEB (4 * BUFB)         // Ah, Al, Bh, Bl
#define DSMEMB (2 * STAGEB)       // double buffered: 81920 B

// ------------------------------- scratch -----------------------------------
__device__ __align__(16) __nv_bfloat16 g_Xh[(size_t)MS * Dv];
__device__ __align__(16) __nv_bfloat16 g_Xl[(size_t)MS * Dv];
__device__ __align__(16) __nv_bfloat16 g_Wqh[(size_t)Dv * DQ];
__device__ __align__(16) __nv_bfloat16 g_Wql[(size_t)Dv * DQ];
__device__ __align__(16) __nv_bfloat16 g_Wkh[(size_t)Dv * DQ];
__device__ __align__(16) __nv_bfloat16 g_Wkl[(size_t)Dv * DQ];
__device__ __align__(16) __nv_bfloat16 g_Wvh[(size_t)Dv * DQ];
__device__ __align__(16) __nv_bfloat16 g_Wvl[(size_t)Dv * DQ];
__device__ __align__(16) float g_Q[(size_t)MS * DQ];
__device__ __align__(16) float g_K[(size_t)MS * DQ];
__device__ __align__(16) float g_V[(size_t)MS * DQ];
__device__ __align__(16) __nv_bfloat16 g_Qh[(size_t)MS * DQ];
__device__ __align__(16) __nv_bfloat16 g_Ql[(size_t)MS * DQ];
__device__ __align__(16) __nv_bfloat16 g_Kh[(size_t)MS * DQ];
__device__ __align__(16) __nv_bfloat16 g_Kl[(size_t)MS * DQ];
__device__ __align__(16) __nv_bfloat16 g_Vth[(size_t)MS * DQ];
__device__ __align__(16) __nv_bfloat16 g_Vtl[(size_t)MS * DQ];
__device__ __align__(16) float g_S[(size_t)Bv * Sv * Sv];
__device__ __align__(16) __nv_bfloat16 g_Ph[(size_t)Bv * Sv * Sv];
__device__ __align__(16) __nv_bfloat16 g_Pl[(size_t)Bv * Sv * Sv];

// ------------------------------ PTX helpers --------------------------------
__device__ __forceinline__ uint32_t smem_u32(const void* p) {
    uint32_t a;
    asm("{ .reg .u64 t; cvta.to.shared.u64 t, %1; cvt.u32.u64 %0, t; }" : "=r"(a) : "l"(p));
    return a;
}
__device__ __forceinline__ void cp16(uint32_t dst, const void* src) {
    asm volatile("cp.async.cg.shared.global [%0], [%1], 16;" :: "r"(dst), "l"(src) : "memory");
}
__device__ __forceinline__ void ldsm4(uint32_t* r, uint32_t addr) {
    asm volatile("ldmatrix.sync.aligned.m8n8.x4.shared.b16 {%0,%1,%2,%3}, [%4];"
                 : "=r"(r[0]), "=r"(r[1]), "=r"(r[2]), "=r"(r[3]) : "r"(addr));
}
__device__ __forceinline__ void mma16816(float* d, const uint32_t* a, uint32_t b0, uint32_t b1) {
    asm volatile(
        "mma.sync.aligned.m16n8k16.row.col.f32.bf16.bf16.f32 "
        "{%0,%1,%2,%3}, {%4,%5,%6,%7}, {%8,%9}, {%0,%1,%2,%3};"
        : "+f"(d[0]), "+f"(d[1]), "+f"(d[2]), "+f"(d[3])
        : "r"(a[0]), "r"(a[1]), "r"(a[2]), "r"(a[3]), "r"(b0), "r"(b1));
}

// ------------------------------ GEMM kernel --------------------------------
// D[m,n] = alpha * sum_k (A[m,k]*B[n,k]), split-bf16 -> fp32.
// grid = (N/128, M/128, batch), block = 256 (8 warps, 64x32 warp tiles).
__global__ __launch_bounds__(GEMM_THREADS)
void gemm_mma(const __nv_bfloat16* __restrict__ Ah, const __nv_bfloat16* __restrict__ Al,
              const __nv_bfloat16* __restrict__ Bh, const __nv_bfloat16* __restrict__ Bl,
              float* __restrict__ C, int Nn, int K, float alpha,
              size_t sA, size_t sB, size_t sC)
{
    extern __shared__ char dsm[];
    const int tid = threadIdx.x;
    const int lane = tid & 31, wid = tid >> 5;

    const size_t aOff = (size_t)blockIdx.z * sA + (size_t)(blockIdx.y * TILE) * K;
    const size_t bOff = (size_t)blockIdx.z * sB + (size_t)(blockIdx.x * TILE) * K;
    const __nv_bfloat16* bases[4] = { Ah + aOff, Al + aOff, Bh + bOff, Bl + bOff };
    C += (size_t)blockIdx.z * sC;

    const uint32_t s0 = smem_u32(dsm);

    // warp tiling: 2 (m) x 4 (n)
    const int wm = wid & 1, wn = wid >> 1;
    const int m0 = wm * 64, n0 = wn * 32;

    float acc[4][4][4];
#pragma unroll
    for (int i = 0; i < 4; i++)
#pragma unroll
        for (int j = 0; j < 4; j++)
#pragma unroll
            for (int q = 0; q < 4; q++) acc[i][j][q] = 0.0f;

    auto load_stage = [&](int s, int kt) {
        const uint32_t base = s0 + (uint32_t)s * STAGEB;
#pragma unroll
        for (int i = 0; i < 8; i++) {
            const int buf = i >> 1;                  // compile-time per i
            const int idx = ((i & 1) << 8) + tid;    // 0..511
            const int r = idx >> 2, c = idx & 3;
            cp16(base + (uint32_t)buf * BUFB + (uint32_t)(r * KPAD + c * 8) * 2,
                 bases[buf] + (size_t)r * K + kt + c * 8);
        }
        asm volatile("cp.async.commit_group;" ::: "memory");
    };

    const int nCh = K / KCH;
    load_stage(0, 0);

    for (int c = 0; c < nCh; ++c) {
        if (c + 1 < nCh) {
            load_stage((c + 1) & 1, (c + 1) * KCH);
            asm volatile("cp.async.wait_group 1;" ::: "memory");
        } else {
            asm volatile("cp.async.wait_group 0;" ::: "memory");
        }
        __syncthreads();

        const uint32_t stg = s0 + (uint32_t)(c & 1) * STAGEB;
        const uint32_t sAh = stg + 0 * BUFB, sAl = stg + 1 * BUFB;
        const uint32_t sBh = stg + 2 * BUFB, sBl = stg + 3 * BUFB;

#pragma unroll
        for (int ks = 0; ks < 2; ks++) {
            const int k0 = ks * 16;
            uint32_t ah[4][4], al[4][4];
#pragma unroll
            for (int mt = 0; mt < 4; mt++) {
                const uint32_t off =
                    (uint32_t)((m0 + mt * 16 + (lane & 15)) * KPAD + k0 + (lane >> 4) * 8) * 2;
                ldsm4(ah[mt], sAh + off);
                ldsm4(al[mt], sAl + off);
            }
            uint32_t bh[2][4], bl[2][4];
#pragma unroll
            for (int p = 0; p < 2; p++) {
                const uint32_t off =
                    (uint32_t)((n0 + p * 16 + (lane & 15)) * KPAD + k0 + (lane >> 4) * 8) * 2;
                ldsm4(bh[p], sBh + off);
                ldsm4(bl[p], sBl + off);
            }
#pragma unroll
            for (int mt = 0; mt < 4; mt++)
#pragma unroll
                for (int nt = 0; nt < 4; nt++) {
                    const int p = nt >> 1, q = nt & 1;
                    mma16816(acc[mt][nt], ah[mt], bh[p][q], bh[p][q + 2]);
                    mma16816(acc[mt][nt], ah[mt], bl[p][q], bl[p][q + 2]);
                    mma16816(acc[mt][nt], al[mt], bh[p][q], bh[p][q + 2]);
                }
        }
        __syncthreads();
    }

    // Epilogue: direct fp32 stores (float2 per fragment row)
    const int mGrp = lane >> 2, nGrp = (lane & 3) * 2;
#pragma unroll
    for (int mt = 0; mt < 4; mt++) {
        const int m = blockIdx.y * TILE + m0 + mt * 16 + mGrp;
#pragma unroll
        for (int nt = 0; nt < 4; nt++) {
            const int n = blockIdx.x * TILE + n0 + nt * 8 + nGrp;
            float2 v0 = { acc[mt][nt][0] * alpha, acc[mt][nt][1] * alpha };
            float2 v1 = { acc[mt][nt][2] * alpha, acc[mt][nt][3] * alpha };
            *reinterpret_cast<float2*>(&C[(size_t)m * Nn + n]) = v0;
            *reinterpret_cast<float2*>(&C[(size_t)(m + 8) * Nn + n]) = v1;
        }
    }
}

// ------------------------- elementwise split kernels -----------------------
__device__ __forceinline__ void split1(float v, __nv_bfloat16& h, __nv_bfloat16& l) {
    h = __float2bfloat16_rn(v);
    l = __float2bfloat16_rn(v - __bfloat162float(h));
}

__global__ __launch_bounds__(256)
void split_kernel(const float* __restrict__ in, __nv_bfloat16* __restrict__ hi,
                  __nv_bfloat16* __restrict__ lo, size_t n)
{
    size_t i = ((size_t)blockIdx.x * 256 + threadIdx.x) * 4;
    if (i >= n) return;
    float4 v = *reinterpret_cast<const float4*>(in + i);
    __nv_bfloat16 h0, h1, h2, h3, l0, l1, l2, l3;
    split1(v.x, h0, l0); split1(v.y, h1, l1); split1(v.z, h2, l2); split1(v.w, h3, l3);
    __nv_bfloat162* ph = reinterpret_cast<__nv_bfloat162*>(hi + i);
    __nv_bfloat162* pl = reinterpret_cast<__nv_bfloat162*>(lo + i);
    __nv_bfloat162 a; a.x = h0; a.y = h1; ph[0] = a;
    __nv_bfloat162 b; b.x = h2; b.y = h3; ph[1] = b;
    __nv_bfloat162 c; c.x = l0; c.y = l1; pl[0] = c;
    __nv_bfloat162 d; d.x = l2; d.y = l3; pl[1] = d;
}

// Transpose + split: in [R,C] row-major -> out [C,R] hi/lo. grid(C/32, R/32, batch)
__global__ __launch_bounds__(256)
void splitT_kernel(const float* __restrict__ in, __nv_bfloat16* __restrict__ hi,
                   __nv_bfloat16* __restrict__ lo, int R, int C)
{
    in += (size_t)blockIdx.z * R * C;
    hi += (size_t)blockIdx.z * R * C;
    lo += (size_t)blockIdx.z * R * C;
    __shared__ float t[32][33];
    const int tx = threadIdx.x, ty = threadIdx.y;
    const int x0 = blockIdx.x * 32, y0 = blockIdx.y * 32;
#pragma unroll
    for (int j = ty; j < 32; j += 8)
        t[j][tx] = in[(size_t)(y0 + j) * C + x0 + tx];
    __syncthreads();
#pragma unroll
    for (int j = ty; j < 32; j += 8) {
        float v = t[tx][j];
        __nv_bfloat16 h, l;
        split1(v, h, l);
        const size_t o = (size_t)(x0 + j) * R + y0 + tx;
        hi[o] = h; lo[o] = l;
    }
}

// ------------------------------- softmax -----------------------------------
__global__ __launch_bounds__(256)
void softmax_split_kernel(float* __restrict__ S, __nv_bfloat16* __restrict__ Ph,
                          __nv_bfloat16* __restrict__ Pl, int n)
{
    float* row = S + (size_t)blockIdx.x * n;
    __nv_bfloat16* ph = Ph + (size_t)blockIdx.x * n;
    __nv_bfloat16* pl = Pl + (size_t)blockIdx.x * n;
    const int tid = threadIdx.x;
    __shared__ float red[256];

    float lmax = -1e30f;
    for (int i = tid * 4; i < n; i += 1024) {
        float4 v = *reinterpret_cast<const float4*>(&row[i]);
        lmax = fmaxf(lmax, fmaxf(fmaxf(v.x, v.y), fmaxf(v.z, v.w)));
    }
    red[tid] = lmax;
    __syncthreads();
    for (int s = 128; s > 0; s >>= 1) {
        if (tid < s) red[tid] = fmaxf(red[tid], red[tid + s]);
        __syncthreads();
    }
    const float m = red[0];
    __syncthreads();

    float lsum = 0.0f;
    for (int i = tid * 4; i < n; i += 1024) {
        float4 v = *reinterpret_cast<float4*>(&row[i]);
        v.x = __expf(v.x - m); v.y = __expf(v.y - m);
        v.z = __expf(v.z - m); v.w = __expf(v.w - m);
        lsum += (v.x + v.y) + (v.z + v.w);
        *reinterpret_cast<float4*>(&row[i]) = v;
    }
    red[tid] = lsum;
    __syncthreads();
    for (int s = 128; s > 0; s >>= 1) {
        if (tid < s) red[tid] += red[tid + s];
        __syncthreads();
    }
    const float inv = 1.0f / red[0];

    for (int i = tid * 4; i < n; i += 1024) {
        float4 v = *reinterpret_cast<const float4*>(&row[i]);
        __nv_bfloat16 h0, h1, h2, h3, l0, l1, l2, l3;
        split1(v.x * inv, h0, l0); split1(v.y * inv, h1, l1);
        split1(v.z * inv, h2, l2); split1(v.w * inv, h3, l3);
        __nv_bfloat162 a; a.x = h0; a.y = h1;
        __nv_bfloat162 b; b.x = h2; b.y = h3;
        __nv_bfloat162 c; c.x = l0; c.y = l1;
        __nv_bfloat162 d; d.x = l2; d.y = l3;
        reinterpret_cast<__nv_bfloat162*>(ph + i)[0] = a;
        reinterpret_cast<__nv_bfloat162*>(ph + i)[1] = b;
        reinterpret_cast<__nv_bfloat162*>(pl + i)[0] = c;
        reinterpret_cast<__nv_bfloat162*>(pl + i)[1] = d;
    }
}

// ------------------------------- launcher ----------------------------------
extern "C" void kernel_launch(void* const* d_in, const int* in_sizes, int n_in,
                              void* d_out, int out_size)
{
    const float* x  = (const float*)d_in[0];
    const float* wq = (const float*)d_in[1];
    const float* wk = (const float*)d_in[2];
    const float* wv = (const float*)d_in[3];
    float* out = (float*)d_out;

    static int smem_set = 0;
    if (!smem_set) {
        cudaFuncSetAttribute(gemm_mma, cudaFuncAttributeMaxDynamicSharedMemorySize, DSMEMB);
        smem_set = 1;
    }

    __nv_bfloat16 *Xh, *Xl, *Wqh, *Wql, *Wkh, *Wkl, *Wvh, *Wvl;
    __nv_bfloat16 *Qh, *Ql, *Kh, *Kl, *Vth, *Vtl, *Ph, *Pl;
    float *Q, *K, *V, *S;
    cudaGetSymbolAddress((void**)&Xh, g_Xh);   cudaGetSymbolAddress((void**)&Xl, g_Xl);
    cudaGetSymbolAddress((void**)&Wqh, g_Wqh); cudaGetSymbolAddress((void**)&Wql, g_Wql);
    cudaGetSymbolAddress((void**)&Wkh, g_Wkh); cudaGetSymbolAddress((void**)&Wkl, g_Wkl);
    cudaGetSymbolAddress((void**)&Wvh, g_Wvh); cudaGetSymbolAddress((void**)&Wvl, g_Wvl);
    cudaGetSymbolAddress((void**)&Q, g_Q);     cudaGetSymbolAddress((void**)&K, g_K);
    cudaGetSymbolAddress((void**)&V, g_V);     cudaGetSymbolAddress((void**)&S, g_S);
    cudaGetSymbolAddress((void**)&Qh, g_Qh);   cudaGetSymbolAddress((void**)&Ql, g_Ql);
    cudaGetSymbolAddress((void**)&Kh, g_Kh);   cudaGetSymbolAddress((void**)&Kl, g_Kl);
    cudaGetSymbolAddress((void**)&Vth, g_Vth); cudaGetSymbolAddress((void**)&Vtl, g_Vtl);
    cudaGetSymbolAddress((void**)&Ph, g_Ph);   cudaGetSymbolAddress((void**)&Pl, g_Pl);

    const size_t nX = (size_t)MS * Dv;

    // 1) split X; transpose+split weights (W^T -> [N,K] K-major)
    split_kernel<<<(unsigned)(nX / 1024), 256>>>(x, Xh, Xl, nX);
    {
        dim3 b(32, 8), g(DQ / 32, Dv / 32, 1);
        splitT_kernel<<<g, b>>>(wq, Wqh, Wql, Dv, DQ);
        splitT_kernel<<<g, b>>>(wk, Wkh, Wkl, Dv, DQ);
        splitT_kernel<<<g, b>>>(wv, Wvh, Wvl, Dv, DQ);
    }

    // 2) QKV projections: [8192,1024] x [1024,1024]
    {
        dim3 grid(DQ / TILE, MS / TILE, 1);
        gemm_mma<<<grid, GEMM_THREADS, DSMEMB>>>(Xh, Xl, Wqh, Wql, Q, DQ, Dv, 1.0f, 0, 0, 0);
        gemm_mma<<<grid, GEMM_THREADS, DSMEMB>>>(Xh, Xl, Wkh, Wkl, K, DQ, Dv, 1.0f, 0, 0, 0);
        gemm_mma<<<grid, GEMM_THREADS, DSMEMB>>>(Xh, Xl, Wvh, Wvl, V, DQ, Dv, 1.0f, 0, 0, 0);
    }

    // 3) split Q,K; transpose+split V per batch -> V^T [DQ, S]
    split_kernel<<<(unsigned)(nX / 1024), 256>>>(Q, Qh, Ql, nX);
    split_kernel<<<(unsigned)(nX / 1024), 256>>>(K, Kh, Kl, nX);
    {
        dim3 b(32, 8), g(DQ / 32, Sv / 32, Bv);
        splitT_kernel<<<g, b>>>(V, Vth, Vtl, Sv, DQ);
    }

    // 4) scores S = Q K^T / 32 (batched)
    {
        dim3 grid(Sv / TILE, Sv / TILE, Bv);
        gemm_mma<<<grid, GEMM_THREADS, DSMEMB>>>(
            Qh, Ql, Kh, Kl, S, Sv, DQ, 0.03125f,
            (size_t)Sv * DQ, (size_t)Sv * DQ, (size_t)Sv * Sv);
    }

    // 5) softmax -> P (bf16 hi/lo)
    softmax_split_kernel<<<Bv * Sv, 256>>>(S, Ph, Pl, Sv);

    // 6) O = P V  (P:[S,S], V^T:[DQ,S] K-major)
    {
        dim3 grid(DQ / TILE, Sv / TILE, Bv);
        gemm_mma<<<grid, GEMM_THREADS, DSMEMB>>>(
            Ph, Pl, Vth, Vtl, out, DQ, Sv, 1.0f,
            (size_t)Sv * Sv, (size_t)DQ * Sv, (size_t)Sv * DQ);
    }
}

// round 9
// speedup vs baseline: 2.3427x; 1.0506x over previous
#include <cuda_runtime.h>
#include <cuda_bf16.h>
#include <cstdint>

// ---------------------------------------------------------------------------
// Attention via legacy warp-MMA (mma.sync bf16) with fused split epilogues.
//   O = softmax((X Wq)(X Wk)^T / 32) (X Wv),  B=4 S=2048 D=DQKV=1024, fp32 I/O.
//
// Every GEMM is D[m,n] = sum_k A[m,k]*B[n,k]  (A:[M,K], B:[N,K], both K-major).
// fp32 operands split x = hi + lo (bf16); GEMM = Ah*Bh + Ah*Bl + Al*Bh with
// fp32 accumulators -> ~2e-5 relative error.
// Epilogues: EPI=0 fp32 store; EPI=1 split hi/lo bf16; EPI=2 per-batch
// transposed split hi/lo (for V^T).
// ---------------------------------------------------------------------------

static const int Bv = 4, Sv = 2048, Dv = 1024, DQ = 1024;
static const int MS = Bv * Sv; // 8192

#define TILE 128
#define KCH 32
#define KPAD 40
#define GEMM_THREADS 256
#define BUFB (128 * KPAD * 2)     // 10240 B per operand buffer
#define STAGEB (4 * BUFB)
#define DSMEMB (2 * STAGEB)       // 81920 B (also covers 128x133 fp32 epilogue tile)

// ------------------------------- scratch -----------------------------------
__device__ __align__(16) __nv_bfloat16 g_Xh[(size_t)MS * Dv];
__device__ __align__(16) __nv_bfloat16 g_Xl[(size_t)MS * Dv];
__device__ __align__(16) __nv_bfloat16 g_Wqh[(size_t)Dv * DQ];
__device__ __align__(16) __nv_bfloat16 g_Wql[(size_t)Dv * DQ];
__device__ __align__(16) __nv_bfloat16 g_Wkh[(size_t)Dv * DQ];
__device__ __align__(16) __nv_bfloat16 g_Wkl[(size_t)Dv * DQ];
__device__ __align__(16) __nv_bfloat16 g_Wvh[(size_t)Dv * DQ];
__device__ __align__(16) __nv_bfloat16 g_Wvl[(size_t)Dv * DQ];
__device__ __align__(16) __nv_bfloat16 g_Qh[(size_t)MS * DQ];
__device__ __align__(16) __nv_bfloat16 g_Ql[(size_t)MS * DQ];
__device__ __align__(16) __nv_bfloat16 g_Kh[(size_t)MS * DQ];
__device__ __align__(16) __nv_bfloat16 g_Kl[(size_t)MS * DQ];
__device__ __align__(16) __nv_bfloat16 g_Vth[(size_t)MS * DQ];
__device__ __align__(16) __nv_bfloat16 g_Vtl[(size_t)MS * DQ];
__device__ __align__(16) float g_S[(size_t)Bv * Sv * Sv];
__device__ __align__(16) __nv_bfloat16 g_Ph[(size_t)Bv * Sv * Sv];
__device__ __align__(16) __nv_bfloat16 g_Pl[(size_t)Bv * Sv * Sv];

// ------------------------------ PTX helpers --------------------------------
__device__ __forceinline__ uint32_t smem_u32(const void* p) {
    uint32_t a;
    asm("{ .reg .u64 t; cvta.to.shared.u64 t, %1; cvt.u32.u64 %0, t; }" : "=r"(a) : "l"(p));
    return a;
}
__device__ __forceinline__ void cp16(uint32_t dst, const void* src) {
    asm volatile("cp.async.cg.shared.global [%0], [%1], 16;" :: "r"(dst), "l"(src) : "memory");
}
__device__ __forceinline__ void ldsm4(uint32_t* r, uint32_t addr) {
    asm volatile("ldmatrix.sync.aligned.m8n8.x4.shared.b16 {%0,%1,%2,%3}, [%4];"
                 : "=r"(r[0]), "=r"(r[1]), "=r"(r[2]), "=r"(r[3]) : "r"(addr));
}
__device__ __forceinline__ void mma16816(float* d, const uint32_t* a, uint32_t b0, uint32_t b1) {
    asm volatile(
        "mma.sync.aligned.m16n8k16.row.col.f32.bf16.bf16.f32 "
        "{%0,%1,%2,%3}, {%4,%5,%6,%7}, {%8,%9}, {%0,%1,%2,%3};"
        : "+f"(d[0]), "+f"(d[1]), "+f"(d[2]), "+f"(d[3])
        : "r"(a[0]), "r"(a[1]), "r"(a[2]), "r"(a[3]), "r"(b0), "r"(b1));
}
__device__ __forceinline__ void split1(float v, __nv_bfloat16& h, __nv_bfloat16& l) {
    h = __float2bfloat16_rn(v);
    l = __float2bfloat16_rn(v - __bfloat162float(h));
}

// ------------------------------ GEMM kernel --------------------------------
// grid = (N/128, M/128, batch), block = 256 (8 warps, 64x32 warp tiles).
// EPI: 0 -> Cf fp32 [M,N]; 1 -> Ch/Cl bf16 [M,N]; 2 -> Ch/Cl bf16 [N, Sv]
//      per batch (transposed, batch = m / Sv), used only with z=1, M=B*Sv.
template <int EPI>
__global__ __launch_bounds__(GEMM_THREADS)
void gemm_mma(const __nv_bfloat16* __restrict__ Ah, const __nv_bfloat16* __restrict__ Al,
              const __nv_bfloat16* __restrict__ Bh, const __nv_bfloat16* __restrict__ Bl,
              float* __restrict__ Cf, __nv_bfloat16* __restrict__ Ch,
              __nv_bfloat16* __restrict__ Cl, int Nn, int K, float alpha,
              size_t sA, size_t sB, size_t sC)
{
    extern __shared__ char dsm[];
    const int tid = threadIdx.x;
    const int lane = tid & 31, wid = tid >> 5;

    const size_t aOff = (size_t)blockIdx.z * sA + (size_t)(blockIdx.y * TILE) * K;
    const size_t bOff = (size_t)blockIdx.z * sB + (size_t)(blockIdx.x * TILE) * K;
    const __nv_bfloat16* bases[4] = { Ah + aOff, Al + aOff, Bh + bOff, Bl + bOff };

    const uint32_t s0 = smem_u32(dsm);
    const int wm = wid & 1, wn = wid >> 1;
    const int m0 = wm * 64, n0 = wn * 32;

    float acc[4][4][4];
#pragma unroll
    for (int i = 0; i < 4; i++)
#pragma unroll
        for (int j = 0; j < 4; j++)
#pragma unroll
            for (int q = 0; q < 4; q++) acc[i][j][q] = 0.0f;

    auto load_stage = [&](int s, int kt) {
        const uint32_t base = s0 + (uint32_t)s * STAGEB;
#pragma unroll
        for (int i = 0; i < 8; i++) {
            const int buf = i >> 1;
            const int idx = ((i & 1) << 8) + tid;
            const int r = idx >> 2, c = idx & 3;
            cp16(base + (uint32_t)buf * BUFB + (uint32_t)(r * KPAD + c * 8) * 2,
                 bases[buf] + (size_t)r * K + kt + c * 8);
        }
        asm volatile("cp.async.commit_group;" ::: "memory");
    };

    const int nCh = K / KCH;
    load_stage(0, 0);

    for (int c = 0; c < nCh; ++c) {
        if (c + 1 < nCh) {
            load_stage((c + 1) & 1, (c + 1) * KCH);
            asm volatile("cp.async.wait_group 1;" ::: "memory");
        } else {
            asm volatile("cp.async.wait_group 0;" ::: "memory");
        }
        __syncthreads();

        const uint32_t stg = s0 + (uint32_t)(c & 1) * STAGEB;
        const uint32_t sAh = stg + 0 * BUFB, sAl = stg + 1 * BUFB;
        const uint32_t sBh = stg + 2 * BUFB, sBl = stg + 3 * BUFB;

#pragma unroll
        for (int ks = 0; ks < 2; ks++) {
            const int k0 = ks * 16;
            uint32_t ah[4][4], al[4][4];
#pragma unroll
            for (int mt = 0; mt < 4; mt++) {
                const uint32_t off =
                    (uint32_t)((m0 + mt * 16 + (lane & 15)) * KPAD + k0 + (lane >> 4) * 8) * 2;
                ldsm4(ah[mt], sAh + off);
                ldsm4(al[mt], sAl + off);
            }
            uint32_t bh[2][4], bl[2][4];
#pragma unroll
            for (int p = 0; p < 2; p++) {
                const uint32_t off =
                    (uint32_t)((n0 + p * 16 + (lane & 15)) * KPAD + k0 + (lane >> 4) * 8) * 2;
                ldsm4(bh[p], sBh + off);
                ldsm4(bl[p], sBl + off);
            }
#pragma unroll
            for (int mt = 0; mt < 4; mt++)
#pragma unroll
                for (int nt = 0; nt < 4; nt++) {
                    const int p = nt >> 1, q = nt & 1;
                    mma16816(acc[mt][nt], ah[mt], bh[p][q], bh[p][q + 2]);
                    mma16816(acc[mt][nt], ah[mt], bl[p][q], bl[p][q + 2]);
                    mma16816(acc[mt][nt], al[mt], bh[p][q], bh[p][q + 2]);
                }
        }
        __syncthreads();
    }

    const int mGrp = lane >> 2, nGrp = (lane & 3) * 2;

    if (EPI == 0) {
        float* C = Cf + (size_t)blockIdx.z * sC;
#pragma unroll
        for (int mt = 0; mt < 4; mt++) {
            const int m = blockIdx.y * TILE + m0 + mt * 16 + mGrp;
#pragma unroll
            for (int nt = 0; nt < 4; nt++) {
                const int n = blockIdx.x * TILE + n0 + nt * 8 + nGrp;
                float2 v0 = { acc[mt][nt][0] * alpha, acc[mt][nt][1] * alpha };
                float2 v1 = { acc[mt][nt][2] * alpha, acc[mt][nt][3] * alpha };
                *reinterpret_cast<float2*>(&C[(size_t)m * Nn + n]) = v0;
                *reinterpret_cast<float2*>(&C[(size_t)(m + 8) * Nn + n]) = v1;
            }
        }
    } else if (EPI == 1) {
        // split hi/lo directly from registers, same [M,N] layout
#pragma unroll
        for (int mt = 0; mt < 4; mt++) {
            const int m = blockIdx.y * TILE + m0 + mt * 16 + mGrp;
#pragma unroll
            for (int nt = 0; nt < 4; nt++) {
                const int n = blockIdx.x * TILE + n0 + nt * 8 + nGrp;
#pragma unroll
                for (int half = 0; half < 2; half++) {
                    const size_t o = (size_t)(m + half * 8) * Nn + n;
                    __nv_bfloat16 h0, h1, l0, l1;
                    split1(acc[mt][nt][half * 2 + 0], h0, l0);
                    split1(acc[mt][nt][half * 2 + 1], h1, l1);
                    __nv_bfloat162 hh; hh.x = h0; hh.y = h1;
                    __nv_bfloat162 ll; ll.x = l0; ll.y = l1;
                    *reinterpret_cast<__nv_bfloat162*>(Ch + o) = hh;
                    *reinterpret_cast<__nv_bfloat162*>(Cl + o) = ll;
                }
            }
        }
    } else {
        // EPI == 2: smem transpose stage, then split hi/lo to [N, Sv] per batch
        float* ep = reinterpret_cast<float*>(dsm);   // 128 x 133 fp32 tile
#pragma unroll
        for (int mt = 0; mt < 4; mt++) {
            const int ml = m0 + mt * 16 + mGrp;
#pragma unroll
            for (int nt = 0; nt < 4; nt++) {
                const int nl = n0 + nt * 8 + nGrp;
#pragma unroll
                for (int half = 0; half < 2; half++) {
                    ep[(ml + half * 8) * 133 + nl]     = acc[mt][nt][half * 2 + 0];
                    ep[(ml + half * 8) * 133 + nl + 1] = acc[mt][nt][half * 2 + 1];
                }
            }
        }
        __syncthreads();
        const int mG0 = blockIdx.y * TILE;
        const int b = mG0 / Sv;
        const int sRow = mG0 % Sv;
        __nv_bfloat16* oh = Ch + (size_t)b * Sv * DQ;
        __nv_bfloat16* ol = Cl + (size_t)b * Sv * DQ;
#pragma unroll
        for (int j = 0; j < 64; j++) {
            const int flat = j * 256 + tid;
            const int n = flat >> 7, m = flat & 127;   // lanes vary m -> coalesced
            __nv_bfloat16 h, l;
            split1(ep[m * 133 + n], h, l);
            const size_t o = (size_t)(blockIdx.x * TILE + n) * Sv + sRow + m;
            oh[o] = h; ol[o] = l;
        }
    }
}

// ------------------------- elementwise split kernels -----------------------
__global__ __launch_bounds__(256)
void split_kernel(const float* __restrict__ in, __nv_bfloat16* __restrict__ hi,
                  __nv_bfloat16* __restrict__ lo, size_t n)
{
    size_t i = ((size_t)blockIdx.x * 256 + threadIdx.x) * 4;
    if (i >= n) return;
    float4 v = *reinterpret_cast<const float4*>(in + i);
    __nv_bfloat16 h0, h1, h2, h3, l0, l1, l2, l3;
    split1(v.x, h0, l0); split1(v.y, h1, l1); split1(v.z, h2, l2); split1(v.w, h3, l3);
    __nv_bfloat162* ph = reinterpret_cast<__nv_bfloat162*>(hi + i);
    __nv_bfloat162* pl = reinterpret_cast<__nv_bfloat162*>(lo + i);
    __nv_bfloat162 a; a.x = h0; a.y = h1; ph[0] = a;
    __nv_bfloat162 b; b.x = h2; b.y = h3; ph[1] = b;
    __nv_bfloat162 c; c.x = l0; c.y = l1; pl[0] = c;
    __nv_bfloat162 d; d.x = l2; d.y = l3; pl[1] = d;
}

__global__ __launch_bounds__(256)
void splitT_kernel(const float* __restrict__ in, __nv_bfloat16* __restrict__ hi,
                   __nv_bfloat16* __restrict__ lo, int R, int C)
{
    __shared__ float t[32][33];
    const int tx = threadIdx.x, ty = threadIdx.y;
    const int x0 = blockIdx.x * 32, y0 = blockIdx.y * 32;
#pragma unroll
    for (int j = ty; j < 32; j += 8)
        t[j][tx] = in[(size_t)(y0 + j) * C + x0 + tx];
    __syncthreads();
#pragma unroll
    for (int j = ty; j < 32; j += 8) {
        float v = t[tx][j];
        __nv_bfloat16 h, l;
        split1(v, h, l);
        const size_t o = (size_t)(x0 + j) * R + y0 + tx;
        hi[o] = h; lo[o] = l;
    }
}

// ------------------------------- softmax -----------------------------------
// Row of 2048 fp32 held in registers: one gmem read, one hi/lo write.
__global__ __launch_bounds__(256)
void softmax_split_kernel(const float* __restrict__ S, __nv_bfloat16* __restrict__ Ph,
                          __nv_bfloat16* __restrict__ Pl)
{
    const float4* row = reinterpret_cast<const float4*>(S + (size_t)blockIdx.x * Sv);
    __nv_bfloat162* ph = reinterpret_cast<__nv_bfloat162*>(Ph + (size_t)blockIdx.x * Sv);
    __nv_bfloat162* pl = reinterpret_cast<__nv_bfloat162*>(Pl + (size_t)blockIdx.x * Sv);
    const int tid = threadIdx.x, lane = tid & 31, warp = tid >> 5;
    __shared__ float red[8];

    float4 v0 = row[tid];
    float4 v1 = row[tid + 256];

    float m = fmaxf(fmaxf(fmaxf(v0.x, v0.y), fmaxf(v0.z, v0.w)),
                    fmaxf(fmaxf(v1.x, v1.y), fmaxf(v1.z, v1.w)));
#pragma unroll
    for (int o = 16; o > 0; o >>= 1) m = fmaxf(m, __shfl_xor_sync(~0u, m, o));
    if (lane == 0) red[warp] = m;
    __syncthreads();
    m = red[0];
#pragma unroll
    for (int w = 1; w < 8; w++) m = fmaxf(m, red[w]);

    v0.x = __expf(v0.x - m); v0.y = __expf(v0.y - m);
    v0.z = __expf(v0.z - m); v0.w = __expf(v0.w - m);
    v1.x = __expf(v1.x - m); v1.y = __expf(v1.y - m);
    v1.z = __expf(v1.z - m); v1.w = __expf(v1.w - m);

    float s = (v0.x + v0.y) + (v0.z + v0.w) + (v1.x + v1.y) + (v1.z + v1.w);
#pragma unroll
    for (int o = 16; o > 0; o >>= 1) s += __shfl_xor_sync(~0u, s, o);
    __syncthreads();
    if (lane == 0) red[warp] = s;
    __syncthreads();
    s = red[0];
#pragma unroll
    for (int w = 1; w < 8; w++) s += red[w];
    const float inv = 1.0f / s;

    __nv_bfloat16 h0, h1, l0, l1;
    __nv_bfloat162 hh, ll;
    split1(v0.x * inv, h0, l0); split1(v0.y * inv, h1, l1);
    hh.x = h0; hh.y = h1; ll.x = l0; ll.y = l1;
    ph[tid * 2] = hh; pl[tid * 2] = ll;
    split1(v0.z * inv, h0, l0); split1(v0.w * inv, h1, l1);
    hh.x = h0; hh.y = h1; ll.x = l0; ll.y = l1;
    ph[tid * 2 + 1] = hh; pl[tid * 2 + 1] = ll;
    split1(v1.x * inv, h0, l0); split1(v1.y * inv, h1, l1);
    hh.x = h0; hh.y = h1; ll.x = l0; ll.y = l1;
    ph[tid * 2 + 512] = hh; pl[tid * 2 + 512] = ll;
    split1(v1.z * inv, h0, l0); split1(v1.w * inv, h1, l1);
    hh.x = h0; hh.y = h1; ll.x = l0; ll.y = l1;
    ph[tid * 2 + 513] = hh; pl[tid * 2 + 513] = ll;
}

// ------------------------------- launcher ----------------------------------
extern "C" void kernel_launch(void* const* d_in, const int* in_sizes, int n_in,
                              void* d_out, int out_size)
{
    const float* x  = (const float*)d_in[0];
    const float* wq = (const float*)d_in[1];
    const float* wk = (const float*)d_in[2];
    const float* wv = (const float*)d_in[3];
    float* out = (float*)d_out;

    static int smem_set = 0;
    if (!smem_set) {
        cudaFuncSetAttribute(gemm_mma<0>, cudaFuncAttributeMaxDynamicSharedMemorySize, DSMEMB);
        cudaFuncSetAttribute(gemm_mma<1>, cudaFuncAttributeMaxDynamicSharedMemorySize, DSMEMB);
        cudaFuncSetAttribute(gemm_mma<2>, cudaFuncAttributeMaxDynamicSharedMemorySize, DSMEMB);
        smem_set = 1;
    }

    __nv_bfloat16 *Xh, *Xl, *Wqh, *Wql, *Wkh, *Wkl, *Wvh, *Wvl;
    __nv_bfloat16 *Qh, *Ql, *Kh, *Kl, *Vth, *Vtl, *Ph, *Pl;
    float *S;
    cudaGetSymbolAddress((void**)&Xh, g_Xh);   cudaGetSymbolAddress((void**)&Xl, g_Xl);
    cudaGetSymbolAddress((void**)&Wqh, g_Wqh); cudaGetSymbolAddress((void**)&Wql, g_Wql);
    cudaGetSymbolAddress((void**)&Wkh, g_Wkh); cudaGetSymbolAddress((void**)&Wkl, g_Wkl);
    cudaGetSymbolAddress((void**)&Wvh, g_Wvh); cudaGetSymbolAddress((void**)&Wvl, g_Wvl);
    cudaGetSymbolAddress((void**)&S, g_S);
    cudaGetSymbolAddress((void**)&Qh, g_Qh);   cudaGetSymbolAddress((void**)&Ql, g_Ql);
    cudaGetSymbolAddress((void**)&Kh, g_Kh);   cudaGetSymbolAddress((void**)&Kl, g_Kl);
    cudaGetSymbolAddress((void**)&Vth, g_Vth); cudaGetSymbolAddress((void**)&Vtl, g_Vtl);
    cudaGetSymbolAddress((void**)&Ph, g_Ph);   cudaGetSymbolAddress((void**)&Pl, g_Pl);

    const size_t nX = (size_t)MS * Dv;

    // 1) split X; transpose+split weights (W^T -> [N,K] K-major)
    split_kernel<<<(unsigned)(nX / 1024), 256>>>(x, Xh, Xl, nX);
    {
        dim3 b(32, 8), g(DQ / 32, Dv / 32, 1);
        splitT_kernel<<<g, b>>>(wq, Wqh, Wql, Dv, DQ);
        splitT_kernel<<<g, b>>>(wk, Wkh, Wkl, Dv, DQ);
        splitT_kernel<<<g, b>>>(wv, Wvh, Wvl, Dv, DQ);
    }

    // 2) QKV projections with fused split epilogues
    {
        dim3 grid(DQ / TILE, MS / TILE, 1);
        gemm_mma<1><<<grid, GEMM_THREADS, DSMEMB>>>(
            Xh, Xl, Wqh, Wql, nullptr, Qh, Ql, DQ, Dv, 1.0f, 0, 0, 0);
        gemm_mma<1><<<grid, GEMM_THREADS, DSMEMB>>>(
            Xh, Xl, Wkh, Wkl, nullptr, Kh, Kl, DQ, Dv, 1.0f, 0, 0, 0);
        gemm_mma<2><<<grid, GEMM_THREADS, DSMEMB>>>(
            Xh, Xl, Wvh, Wvl, nullptr, Vth, Vtl, DQ, Dv, 1.0f, 0, 0, 0);
    }

    // 3) scores S = Q K^T / 32 (batched)
    {
        dim3 grid(Sv / TILE, Sv / TILE, Bv);
        gemm_mma<0><<<grid, GEMM_THREADS, DSMEMB>>>(
            Qh, Ql, Kh, Kl, S, nullptr, nullptr, Sv, DQ, 0.03125f,
            (size_t)Sv * DQ, (size_t)Sv * DQ, (size_t)Sv * Sv);
    }

    // 4) softmax -> P (bf16 hi/lo), register-resident rows
    softmax_split_kernel<<<Bv * Sv, 256>>>(S, Ph, Pl);

    // 5) O = P V  (P:[S,S], V^T:[DQ,S] K-major)
    {
        dim3 grid(DQ / TILE, Sv / TILE, Bv);
        gemm_mma<0><<<grid, GEMM_THREADS, DSMEMB>>>(
            Ph, Pl, Vth, Vtl, out, nullptr, nullptr, DQ, Sv, 1.0f,
            (size_t)Sv * Sv, (size_t)DQ * Sv, (size_t)Sv * DQ);
    }
}